// round 16
// baseline (speedup 1.0000x reference)
#include <cuda_runtime.h>

#define TPB 128   // one batch row per thread; warps fully decoupled

__device__ __forceinline__ float fsqrt_ap(float x) {
    float r; asm("sqrt.approx.f32 %0,%1;" : "=f"(r) : "f"(x)); return r;
}
__device__ __forceinline__ float frsqrt_ap(float x) {
    float r; asm("rsqrt.approx.f32 %0,%1;" : "=f"(r) : "f"(x)); return r;
}

struct C { float r, i; };
struct MC { float ar, ai, cr, ci, ct, st; };

__device__ __forceinline__ MC mkmc(float th, float ph) {
    float st, ct, sp, cp;
    __sincosf(th, &st, &ct);
    __sincosf(ph, &sp, &cp);
    MC m;
    m.ct = ct; m.st = st;
    m.ar = cp * ct; m.ai = sp * ct;
    m.cr = cp * st; m.ci = sp * st;
    return m;
}

__device__ __forceinline__ void rot_cc(C& pi, C& pj, const MC& m) {
    float nir = fmaf(m.ar, pi.r, fmaf(-m.ai, pi.i, -m.st * pj.r));
    float nii = fmaf(m.ar, pi.i, fmaf( m.ai, pi.r, -m.st * pj.i));
    float njr = fmaf(m.cr, pi.r, fmaf(-m.ci, pi.i,  m.ct * pj.r));
    float nji = fmaf(m.cr, pi.i, fmaf( m.ci, pi.r,  m.ct * pj.i));
    pi.r = nir; pi.i = nii; pj.r = njr; pj.i = nji;
}
__device__ __forceinline__ void rot_c0(C& pi, C& pj, const MC& m) {
    float nir = fmaf(m.ar, pi.r, -m.ai * pi.i);
    float nii = fmaf(m.ar, pi.i,  m.ai * pi.r);
    pj.r      = fmaf(m.cr, pi.r, -m.ci * pi.i);
    pj.i      = fmaf(m.cr, pi.i,  m.ci * pi.r);
    pi.r = nir; pi.i = nii;
}
__device__ __forceinline__ void rot_rc(float w, C& pi, C& pj, const MC& m) {
    pi.r = fmaf(m.ar, w, -m.st * pj.r);
    pi.i = fmaf(m.ai, w, -m.st * pj.i);
    float njr = fmaf(m.cr, w, m.ct * pj.r);
    float nji = fmaf(m.ci, w, m.ct * pj.i);
    pj.r = njr; pj.i = nji;
}

// pipeline body: xs[12] + spre(29 floats) -> 15 normalized |amp| in sdst
__device__ __forceinline__ void bqnn_body(const float* __restrict__ xs,
                                          const float* __restrict__ spre,
                                          float* __restrict__ sdst) {
    auto ldmc = [&](int q) {
        const float* p = spre + 5 + q * 6;
        MC m;
        m.ar = p[0]; m.ai = p[1];
        m.cr = p[2]; m.ci = p[3];
        m.ct = p[4]; m.st = p[5];
        return m;
    };

    float U0 = spre[0], U1 = spre[1], U2 = spre[2];
    float V3 = spre[3], V4 = spre[4];

    C A0, A1, A2, A3, A4, A5;
    C B1, B2, B3, B4, B5;
    float B0r, B1r, B2r, B3r;

    { // mode4 [0,1] (data)
        MC m = mkmc(xs[3], xs[0]);
        A0.r = fmaf(m.ar, U0, -m.st * U1); A0.i = m.ai * U0;
        A1.r = fmaf(m.cr, U0,  m.ct * U1); A1.i = m.ci * U0;
    }
    { // mode5 [2,3] (data)
        MC m = mkmc(xs[4], xs[1]);
        A2.r = m.ar * U2; A2.i = m.ai * U2;
        A3.r = m.cr * U2; A3.i = m.ci * U2;
        B2r = -m.st * V3; B3r = m.ct * V3;
    }
    { // mode6 [4,5] (data)
        MC m = mkmc(xs[5], xs[2]);
        B4.r = m.ar * V4; B4.i = m.ai * V4;
        B5.r = m.cr * V4; B5.i = m.ci * V4;
    }
    { // mode7 [1,2] (uniform q0)
        MC u = ldmc(0);
        rot_cc(A1, A2, u);
        B1r = -u.st * B2r;
        B2r =  u.ct * B2r;
    }
    { // mode8 [3,4] (uniform q1)
        MC u = ldmc(1);
        rot_c0(A3, A4, u);
        rot_rc(B3r, B3, B4, u);
    }
    { // mode9 [0,1] (data)
        MC m = mkmc(xs[9], xs[6]);
        rot_cc(A0, A1, m);
        B0r = -m.st * B1r;
        B1r =  m.ct * B1r;
    }
    { // mode10 [2,3] (data)
        MC m = mkmc(xs[10], xs[7]);
        rot_cc(A2, A3, m);
        rot_rc(B2r, B2, B3, m);
    }
    { // mode11 [4,5] (data)
        MC m = mkmc(xs[11], xs[8]);
        rot_c0(A4, A5, m);
        rot_cc(B4, B5, m);
    }
    { // mode12 [1,2] (uniform q2)
        MC u = ldmc(2);
        rot_cc(A1, A2, u);
        rot_rc(B1r, B1, B2, u);
    }
    { // mode13 [3,4] (uniform q3)
        MC u = ldmc(3);
        rot_cc(A3, A4, u);
        rot_cc(B3, B4, u);
    }

    // transform to (p, q, sqrt2*Re c, sqrt2*Im c)
    float pp[6], qq[6], cs[6], cis[6];
    {
        float a_r[6] = {A0.r, A1.r, A2.r, A3.r, A4.r, A5.r};
        float a_i[6] = {A0.i, A1.i, A2.i, A3.i, A4.i, A5.i};
        float b_r[6] = {B0r,  B1.r, B2.r, B3.r, B4.r, B5.r};
        float b_i[6] = {0.f,  B1.i, B2.i, B3.i, B4.i, B5.i};
        const float RT2 = 1.41421356237f;
#pragma unroll
        for (int k = 0; k < 6; k++) {
            float ar = a_r[k], ai = a_i[k], br = b_r[k], bi = b_i[k];
            pp[k]  = fmaf(ar, ar, ai * ai);
            qq[k]  = fmaf(br, br, bi * bi);
            cs[k]  = RT2 * fmaf(ar, br,  ai * bi);
            cis[k] = RT2 * fmaf(ai, br, -ar * bi);
        }
    }

    // analytic norm: sum |amp|^2 = 1 - 2*sum_k p_k q_k
    float dot = 0.f;
#pragma unroll
    for (int k = 0; k < 6; k++) dot = fmaf(pp[k], qq[k], dot);
    float rn = frsqrt_ap(fmaxf(fmaf(-2.f, dot, 1.f), 1e-24f));

    const int PA[15] = {0, 0, 0, 0, 0, 1, 1, 1, 1, 2, 2, 2, 3, 3, 4};
    const int PB[15] = {1, 2, 3, 4, 5, 2, 3, 4, 5, 3, 4, 5, 4, 5, 5};
#pragma unroll
    for (int p = 0; p < 15; p++) {
        const int i = PA[p], j = PB[p];
        float mag = fmaf(pp[i], qq[j],
                     fmaf(pp[j], qq[i],
                      fmaf(cs[i], cs[j], cis[i] * cis[j])));
        sdst[p] = fsqrt_ap(fmaxf(mag, 0.f)) * rn;
    }
}

// per-warp uniform precompute: lanes 0..4 fill this warp's 29-float spre slice
__device__ __forceinline__ void fill_spre_warp(int lane,
                                               const float* __restrict__ pphi,
                                               const float* __restrict__ pth,
                                               float* __restrict__ spre) {
    if (lane < 4) {
        float th = __ldg(pth + 4 + lane), ph = __ldg(pphi + lane);
        float st, ct, sp, cp;
        __sincosf(th, &st, &ct);
        __sincosf(ph, &sp, &cp);
        float* o = spre + 5 + lane * 6;
        o[0] = cp * ct; o[1] = sp * ct;
        o[2] = cp * st; o[3] = sp * st;
        o[4] = ct;      o[5] = st;
    } else if (lane == 4) {
        float st0, ct0, st2, ct2, st3, ct3;
        __sincosf(__ldg(pth + 0), &st0, &ct0);
        __sincosf(__ldg(pth + 2), &st2, &ct2);
        __sincosf(__ldg(pth + 3), &st3, &ct3);
        spre[0] = ct0;
        spre[1] = ct2 * st0;
        spre[2] = st2 * st0;
        spre[3] = ct3;
        spre[4] = st3;
    }
}

// ---------- fast path: batch % TPB == 0 (no guards, warp-decoupled) ----------
__global__ __launch_bounds__(TPB, 8)
void bqnn_fast(const float* __restrict__ x,
               const float* __restrict__ pphi,
               const float* __restrict__ pth,
               const float* __restrict__ ink,
               const float* __restrict__ inb,
               float* __restrict__ out) {
    __shared__ float sout[TPB * 15];         // 4 warp slices of 480 floats
    __shared__ float spre[4][32];            // per-warp 29-float slice (padded)
    const int t    = threadIdx.x;
    const int warp = t >> 5;
    const int lane = t & 31;
    const int row  = blockIdx.x * TPB + t;

    fill_spre_warp(lane, pphi, pth, spre[warp]);

    float xs[12];
    {
        float4 k0 = __ldg((const float4*)(ink + 0));
        float4 k1 = __ldg((const float4*)(ink + 4));
        float4 k2 = __ldg((const float4*)(ink + 8));
        float4 b0 = __ldg((const float4*)(inb + 0));
        float4 b1 = __ldg((const float4*)(inb + 4));
        float4 b2 = __ldg((const float4*)(inb + 8));
        const float4* xp = (const float4*)(x + (size_t)row * 12);
        float4 x0 = xp[0], x1 = xp[1], x2 = xp[2];
        xs[0]  = fmaf(x0.x, k0.x, b0.x);
        xs[1]  = fmaf(x0.y, k0.y, b0.y);
        xs[2]  = fmaf(x0.z, k0.z, b0.z);
        xs[3]  = fmaf(x0.w, k0.w, b0.w);
        xs[4]  = fmaf(x1.x, k1.x, b1.x);
        xs[5]  = fmaf(x1.y, k1.y, b1.y);
        xs[6]  = fmaf(x1.z, k1.z, b1.z);
        xs[7]  = fmaf(x1.w, k1.w, b1.w);
        xs[8]  = fmaf(x2.x, k2.x, b2.x);
        xs[9]  = fmaf(x2.y, k2.y, b2.y);
        xs[10] = fmaf(x2.z, k2.z, b2.z);
        xs[11] = fmaf(x2.w, k2.w, b2.w);
    }

    __syncwarp();
    bqnn_body(xs, spre[warp], sout + 15 * t);
    __syncwarp();

    // per-warp coalesced copy-out: 480 floats = 120 float4 by 32 lanes
    const float4* s4 = (const float4*)(sout + warp * 480);
    float4* g4 = (float4*)(out + ((size_t)blockIdx.x * TPB + warp * 32) * 15);
    g4[lane]      = s4[lane];
    g4[lane + 32] = s4[lane + 32];
    g4[lane + 64] = s4[lane + 64];
    if (lane < 24) g4[lane + 96] = s4[lane + 96];
}

// ---------- generic guarded path ----------
__global__ __launch_bounds__(TPB, 8)
void bqnn_gen(const float* __restrict__ x,
              const float* __restrict__ pphi,
              const float* __restrict__ pth,
              const float* __restrict__ ink,
              const float* __restrict__ inb,
              float* __restrict__ out,
              int batch) {
    __shared__ float sout[TPB * 15];
    __shared__ float spre[4][32];
    const int t    = threadIdx.x;
    const int warp = t >> 5;
    const int lane = t & 31;
    const int base = blockIdx.x * TPB;
    const int row  = base + t;

    fill_spre_warp(lane, pphi, pth, spre[warp]);

    float xs[12];
    {
        float4 k0 = __ldg((const float4*)(ink + 0));
        float4 k1 = __ldg((const float4*)(ink + 4));
        float4 k2 = __ldg((const float4*)(ink + 8));
        float4 b0 = __ldg((const float4*)(inb + 0));
        float4 b1 = __ldg((const float4*)(inb + 4));
        float4 b2 = __ldg((const float4*)(inb + 8));
        float4 x0 = make_float4(0.f,0.f,0.f,0.f), x1 = x0, x2 = x0;
        if (row < batch) {
            const float4* xp = (const float4*)(x + (size_t)row * 12);
            x0 = xp[0]; x1 = xp[1]; x2 = xp[2];
        }
        xs[0]  = fmaf(x0.x, k0.x, b0.x);
        xs[1]  = fmaf(x0.y, k0.y, b0.y);
        xs[2]  = fmaf(x0.z, k0.z, b0.z);
        xs[3]  = fmaf(x0.w, k0.w, b0.w);
        xs[4]  = fmaf(x1.x, k1.x, b1.x);
        xs[5]  = fmaf(x1.y, k1.y, b1.y);
        xs[6]  = fmaf(x1.z, k1.z, b1.z);
        xs[7]  = fmaf(x1.w, k1.w, b1.w);
        xs[8]  = fmaf(x2.x, k2.x, b2.x);
        xs[9]  = fmaf(x2.y, k2.y, b2.y);
        xs[10] = fmaf(x2.z, k2.z, b2.z);
        xs[11] = fmaf(x2.w, k2.w, b2.w);
    }

    __syncwarp();
    bqnn_body(xs, spre[warp], sout + 15 * t);
    __syncwarp();

    // per-warp guarded copy-out
    int wbase = base + warp * 32;
    int wrows = batch - wbase;
    if (wrows > 32) wrows = 32;
    if (wrows > 0) {
        float* gout = out + (size_t)wbase * 15;
        const float* s = sout + warp * 480;
        for (int idx = lane; idx < wrows * 15; idx += 32) gout[idx] = s[idx];
    }
}

extern "C" void kernel_launch(void* const* d_in, const int* in_sizes, int n_in,
                              void* d_out, int out_size) {
    const float* x    = (const float*)d_in[0];
    const float* pphi = (const float*)d_in[1];
    const float* pth  = (const float*)d_in[2];
    const float* ink  = (const float*)d_in[3];
    const float* inb  = (const float*)d_in[4];
    float* out = (float*)d_out;

    int batch = in_sizes[0] / 12;
    if (batch % TPB == 0) {
        bqnn_fast<<<batch / TPB, TPB>>>(x, pphi, pth, ink, inb, out);
    } else {
        bqnn_gen<<<(batch + TPB - 1) / TPB, TPB>>>(x, pphi, pth, ink, inb, out, batch);
    }
}

// round 17
// speedup vs baseline: 1.0239x; 1.0239x over previous
#include <cuda_runtime.h>

#define TPB 128   // one batch row per thread

__device__ __forceinline__ float fsqrt_ap(float x) {
    float r; asm("sqrt.approx.f32 %0,%1;" : "=f"(r) : "f"(x)); return r;
}
__device__ __forceinline__ float frsqrt_ap(float x) {
    float r; asm("rsqrt.approx.f32 %0,%1;" : "=f"(r) : "f"(x)); return r;
}

struct C { float r, i; };
struct MC { float ar, ai, cr, ci, ct, st; };

__device__ __forceinline__ MC mkmc(float th, float ph) {
    float st, ct, sp, cp;
    __sincosf(th, &st, &ct);
    __sincosf(ph, &sp, &cp);
    MC m;
    m.ct = ct; m.st = st;
    m.ar = cp * ct; m.ai = sp * ct;
    m.cr = cp * st; m.ci = sp * st;
    return m;
}

__device__ __forceinline__ void rot_cc(C& pi, C& pj, const MC& m) {
    float nir = fmaf(m.ar, pi.r, fmaf(-m.ai, pi.i, -m.st * pj.r));
    float nii = fmaf(m.ar, pi.i, fmaf( m.ai, pi.r, -m.st * pj.i));
    float njr = fmaf(m.cr, pi.r, fmaf(-m.ci, pi.i,  m.ct * pj.r));
    float nji = fmaf(m.cr, pi.i, fmaf( m.ci, pi.r,  m.ct * pj.i));
    pi.r = nir; pi.i = nii; pj.r = njr; pj.i = nji;
}
__device__ __forceinline__ void rot_c0(C& pi, C& pj, const MC& m) {
    float nir = fmaf(m.ar, pi.r, -m.ai * pi.i);
    float nii = fmaf(m.ar, pi.i,  m.ai * pi.r);
    pj.r      = fmaf(m.cr, pi.r, -m.ci * pi.i);
    pj.i      = fmaf(m.cr, pi.i,  m.ci * pi.r);
    pi.r = nir; pi.i = nii;
}
__device__ __forceinline__ void rot_rc(float w, C& pi, C& pj, const MC& m) {
    pi.r = fmaf(m.ar, w, -m.st * pj.r);
    pi.i = fmaf(m.ai, w, -m.st * pj.i);
    float njr = fmaf(m.cr, w, m.ct * pj.r);
    float nji = fmaf(m.ci, w, m.ct * pj.i);
    pj.r = njr; pj.i = nji;
}

// shared pipeline body: from xs[12] + spre -> 15 normalized |amp| in sdst
__device__ __forceinline__ void bqnn_body(const float* __restrict__ xs,
                                          const float* __restrict__ spre,
                                          float* __restrict__ sdst) {
    auto ldmc = [&](int q) {
        const float* p = spre + 5 + q * 6;
        MC m;
        m.ar = p[0]; m.ai = p[1];
        m.cr = p[2]; m.ci = p[3];
        m.ct = p[4]; m.st = p[5];
        return m;
    };

    float U0 = spre[0], U1 = spre[1], U2 = spre[2];
    float V3 = spre[3], V4 = spre[4];

    C A0, A1, A2, A3, A4, A5;
    C B1, B2, B3, B4, B5;
    float B0r, B1r, B2r, B3r;

    { // mode4 [0,1] (data)
        MC m = mkmc(xs[3], xs[0]);
        A0.r = fmaf(m.ar, U0, -m.st * U1); A0.i = m.ai * U0;
        A1.r = fmaf(m.cr, U0,  m.ct * U1); A1.i = m.ci * U0;
    }
    { // mode5 [2,3] (data)
        MC m = mkmc(xs[4], xs[1]);
        A2.r = m.ar * U2; A2.i = m.ai * U2;
        A3.r = m.cr * U2; A3.i = m.ci * U2;
        B2r = -m.st * V3; B3r = m.ct * V3;
    }
    { // mode6 [4,5] (data)
        MC m = mkmc(xs[5], xs[2]);
        B4.r = m.ar * V4; B4.i = m.ai * V4;
        B5.r = m.cr * V4; B5.i = m.ci * V4;
    }
    { // mode7 [1,2] (uniform q0)
        MC u = ldmc(0);
        rot_cc(A1, A2, u);
        B1r = -u.st * B2r;
        B2r =  u.ct * B2r;
    }
    { // mode8 [3,4] (uniform q1)
        MC u = ldmc(1);
        rot_c0(A3, A4, u);
        rot_rc(B3r, B3, B4, u);
    }
    { // mode9 [0,1] (data)
        MC m = mkmc(xs[9], xs[6]);
        rot_cc(A0, A1, m);
        B0r = -m.st * B1r;
        B1r =  m.ct * B1r;
    }
    { // mode10 [2,3] (data)
        MC m = mkmc(xs[10], xs[7]);
        rot_cc(A2, A3, m);
        rot_rc(B2r, B2, B3, m);
    }
    { // mode11 [4,5] (data)
        MC m = mkmc(xs[11], xs[8]);
        rot_c0(A4, A5, m);
        rot_cc(B4, B5, m);
    }
    { // mode12 [1,2] (uniform q2)
        MC u = ldmc(2);
        rot_cc(A1, A2, u);
        rot_rc(B1r, B1, B2, u);
    }
    { // mode13 [3,4] (uniform q3)
        MC u = ldmc(3);
        rot_cc(A3, A4, u);
        rot_cc(B3, B4, u);
    }

    // transform to (p, q, sqrt2*Re c, sqrt2*Im c)
    float pp[6], qq[6], cs[6], cis[6];
    {
        float a_r[6] = {A0.r, A1.r, A2.r, A3.r, A4.r, A5.r};
        float a_i[6] = {A0.i, A1.i, A2.i, A3.i, A4.i, A5.i};
        float b_r[6] = {B0r,  B1.r, B2.r, B3.r, B4.r, B5.r};
        float b_i[6] = {0.f,  B1.i, B2.i, B3.i, B4.i, B5.i};
        const float RT2 = 1.41421356237f;
#pragma unroll
        for (int k = 0; k < 6; k++) {
            float ar = a_r[k], ai = a_i[k], br = b_r[k], bi = b_i[k];
            pp[k]  = fmaf(ar, ar, ai * ai);
            qq[k]  = fmaf(br, br, bi * bi);
            cs[k]  = RT2 * fmaf(ar, br,  ai * bi);
            cis[k] = RT2 * fmaf(ai, br, -ar * bi);
        }
    }

    // analytic norm: sum |amp|^2 = 1 - 2*sum_k p_k q_k
    float dot = 0.f;
#pragma unroll
    for (int k = 0; k < 6; k++) dot = fmaf(pp[k], qq[k], dot);
    float rn = frsqrt_ap(fmaxf(fmaf(-2.f, dot, 1.f), 1e-24f));

    const int PA[15] = {0, 0, 0, 0, 0, 1, 1, 1, 1, 2, 2, 2, 3, 3, 4};
    const int PB[15] = {1, 2, 3, 4, 5, 2, 3, 4, 5, 3, 4, 5, 4, 5, 5};
#pragma unroll
    for (int p = 0; p < 15; p++) {
        const int i = PA[p], j = PB[p];
        float mag = fmaf(pp[i], qq[j],
                     fmaf(pp[j], qq[i],
                      fmaf(cs[i], cs[j], cis[i] * cis[j])));
        sdst[p] = fsqrt_ap(fmaxf(mag, 0.f)) * rn;
    }
}

// uniform precompute into spre (threads 0..4)
__device__ __forceinline__ void fill_spre(int t,
                                          const float* __restrict__ pphi,
                                          const float* __restrict__ pth,
                                          float* __restrict__ spre) {
    if (t < 4) {
        float th = __ldg(pth + 4 + t), ph = __ldg(pphi + t);
        float st, ct, sp, cp;
        __sincosf(th, &st, &ct);
        __sincosf(ph, &sp, &cp);
        float* o = spre + 5 + t * 6;
        o[0] = cp * ct; o[1] = sp * ct;
        o[2] = cp * st; o[3] = sp * st;
        o[4] = ct;      o[5] = st;
    } else if (t == 4) {
        float st0, ct0, st2, ct2, st3, ct3;
        __sincosf(__ldg(pth + 0), &st0, &ct0);
        __sincosf(__ldg(pth + 2), &st2, &ct2);
        __sincosf(__ldg(pth + 3), &st3, &ct3);
        spre[0] = ct0;
        spre[1] = ct2 * st0;
        spre[2] = st2 * st0;
        spre[3] = ct3;
        spre[4] = st3;
    }
}

// ---------- fast path: batch % TPB == 0 (no guards anywhere) ----------
__global__ __launch_bounds__(TPB, 9)
void bqnn_fast(const float* __restrict__ x,
               const float* __restrict__ pphi,
               const float* __restrict__ pth,
               const float* __restrict__ ink,
               const float* __restrict__ inb,
               float* __restrict__ out) {
    __shared__ float sout[TPB * 15];
    __shared__ float spre[5 + 4 * 6];
    const int t = threadIdx.x;
    const int row = blockIdx.x * TPB + t;

    // issue the long-latency x load FIRST so it overlaps the sincos precompute
    const float4* xp = (const float4*)(x + (size_t)row * 12);
    float4 x0 = xp[0], x1 = xp[1], x2 = xp[2];

    fill_spre(t, pphi, pth, spre);

    float xs[12];
    {
        float4 k0 = __ldg((const float4*)(ink + 0));
        float4 k1 = __ldg((const float4*)(ink + 4));
        float4 k2 = __ldg((const float4*)(ink + 8));
        float4 b0 = __ldg((const float4*)(inb + 0));
        float4 b1 = __ldg((const float4*)(inb + 4));
        float4 b2 = __ldg((const float4*)(inb + 8));
        xs[0]  = fmaf(x0.x, k0.x, b0.x);
        xs[1]  = fmaf(x0.y, k0.y, b0.y);
        xs[2]  = fmaf(x0.z, k0.z, b0.z);
        xs[3]  = fmaf(x0.w, k0.w, b0.w);
        xs[4]  = fmaf(x1.x, k1.x, b1.x);
        xs[5]  = fmaf(x1.y, k1.y, b1.y);
        xs[6]  = fmaf(x1.z, k1.z, b1.z);
        xs[7]  = fmaf(x1.w, k1.w, b1.w);
        xs[8]  = fmaf(x2.x, k2.x, b2.x);
        xs[9]  = fmaf(x2.y, k2.y, b2.y);
        xs[10] = fmaf(x2.z, k2.z, b2.z);
        xs[11] = fmaf(x2.w, k2.w, b2.w);
    }

    __syncthreads();
    bqnn_body(xs, spre, sout + 15 * t);
    __syncthreads();

    // exact copy-out: 480 float4 per block = 3 full rounds + 96-thread remainder
    const float4* s4 = (const float4*)sout;
    float4* g4 = (float4*)(out + (size_t)blockIdx.x * (TPB * 15));
    g4[t]           = s4[t];
    g4[t + TPB]     = s4[t + TPB];
    g4[t + 2 * TPB] = s4[t + 2 * TPB];
    if (t < (TPB * 15) / 4 - 3 * TPB)
        g4[t + 3 * TPB] = s4[t + 3 * TPB];
}

// ---------- generic guarded path ----------
__global__ __launch_bounds__(TPB, 9)
void bqnn_gen(const float* __restrict__ x,
              const float* __restrict__ pphi,
              const float* __restrict__ pth,
              const float* __restrict__ ink,
              const float* __restrict__ inb,
              float* __restrict__ out,
              int batch) {
    __shared__ float sout[TPB * 15];
    __shared__ float spre[5 + 4 * 6];
    const int t = threadIdx.x;
    const int base = blockIdx.x * TPB;
    const int row = base + t;

    float4 x0 = make_float4(0.f,0.f,0.f,0.f), x1 = x0, x2 = x0;
    if (row < batch) {
        const float4* xp = (const float4*)(x + (size_t)row * 12);
        x0 = xp[0]; x1 = xp[1]; x2 = xp[2];
    }

    fill_spre(t, pphi, pth, spre);

    float xs[12];
    {
        float4 k0 = __ldg((const float4*)(ink + 0));
        float4 k1 = __ldg((const float4*)(ink + 4));
        float4 k2 = __ldg((const float4*)(ink + 8));
        float4 b0 = __ldg((const float4*)(inb + 0));
        float4 b1 = __ldg((const float4*)(inb + 4));
        float4 b2 = __ldg((const float4*)(inb + 8));
        xs[0]  = fmaf(x0.x, k0.x, b0.x);
        xs[1]  = fmaf(x0.y, k0.y, b0.y);
        xs[2]  = fmaf(x0.z, k0.z, b0.z);
        xs[3]  = fmaf(x0.w, k0.w, b0.w);
        xs[4]  = fmaf(x1.x, k1.x, b1.x);
        xs[5]  = fmaf(x1.y, k1.y, b1.y);
        xs[6]  = fmaf(x1.z, k1.z, b1.z);
        xs[7]  = fmaf(x1.w, k1.w, b1.w);
        xs[8]  = fmaf(x2.x, k2.x, b2.x);
        xs[9]  = fmaf(x2.y, k2.y, b2.y);
        xs[10] = fmaf(x2.z, k2.z, b2.z);
        xs[11] = fmaf(x2.w, k2.w, b2.w);
    }

    __syncthreads();
    bqnn_body(xs, spre, sout + 15 * t);
    __syncthreads();

    int rows = batch - base;
    if (rows > TPB) rows = TPB;
    float* gout = out + (size_t)base * 15;
    for (int idx = t; idx < rows * 15; idx += TPB) gout[idx] = sout[idx];
}

extern "C" void kernel_launch(void* const* d_in, const int* in_sizes, int n_in,
                              void* d_out, int out_size) {
    const float* x    = (const float*)d_in[0];
    const float* pphi = (const float*)d_in[1];
    const float* pth  = (const float*)d_in[2];
    const float* ink  = (const float*)d_in[3];
    const float* inb  = (const float*)d_in[4];
    float* out = (float*)d_out;

    int batch = in_sizes[0] / 12;
    if (batch % TPB == 0) {
        bqnn_fast<<<batch / TPB, TPB>>>(x, pphi, pth, ink, inb, out);
    } else {
        bqnn_gen<<<(batch + TPB - 1) / TPB, TPB>>>(x, pphi, pth, ink, inb, out, batch);
    }
}